// round 3
// baseline (speedup 1.0000x reference)
#include <cuda_runtime.h>

#define H       64
#define NSEG    1024
#define LPB     192      // lanes per block == threads
#define NWARP   (LPB / 32)
#define XROW    33       // padded smem row (33 floats) -> conflict-free

// ---------------- scratch (no allocations allowed) ----------------
__device__ float g_seg_sum[NSEG + 1];  // +1 = dump slot for out-of-range lanes

// ---------------- kernel 0: init ----------------
__global__ void init_kernel(float* __restrict__ out, int out_size) {
    int i = blockIdx.x * blockDim.x + threadIdx.x;
    if (i < out_size) out[i] = 0.0f;
    if (i <= NSEG) g_seg_sum[i] = 0.0f;
}

// ---------------- kernel 1: fused score + exp + seg-sum + unnormalized pool --
__global__ __launch_bounds__(LPB) void fused_kernel(
    const float* __restrict__ ht, const float* __restrict__ info,
    const float* __restrict__ fut, const int* __restrict__ seg,
    const float* __restrict__ w1, const float* __restrict__ b1,
    const float* __restrict__ w2, const float* __restrict__ b2,
    float* __restrict__ out, int M)
{
    __shared__ __align__(16) float w1s[128 * 16];
    __shared__ __align__(16) float b1s[16];
    __shared__ __align__(16) float w2s[16];
    __shared__ float b2s;
    __shared__ __align__(16) float xs[LPB * XROW];   // 32-col chunk staging
    __shared__ float ex_s[LPB];
    __shared__ int   seg_s[LPB];
    __shared__ int   run_start[LPB + 1];
    __shared__ int   warp_cnt[NWARP];
    __shared__ int   nruns_s;

    const int tid = threadIdx.x;
    const int base = blockIdx.x * LPB;
    int nl = M - base;
    if (nl > LPB) nl = LPB;

    // ---- load MLP weights ----
    for (int i = tid; i < 128 * 16; i += LPB) w1s[i] = w1[i];
    if (tid < 16) { b1s[tid] = b1[tid]; w2s[tid] = w2[tid]; }
    if (tid == 0) b2s = b2[0];
    __syncthreads();

    // ---- phase 1: MLP with packed f32x2 accumulators ----
    // hp[q] holds hidden units (2q, 2q+1) as packed f32x2
    unsigned long long hp[8];
#pragma unroll
    for (int q = 0; q < 8; q++)
        hp[q] = reinterpret_cast<const unsigned long long*>(b1s)[q];

#pragma unroll
    for (int chunk = 0; chunk < 4; chunk++) {
        const float* src = (chunk < 2) ? ht : info;
        const int coff4 = (chunk & 1) * 8;           // float4 offset within row
        const int kbase = chunk * 32;                // column offset in [0,128)

        __syncthreads();                             // xs reuse barrier
        // cooperative coalesced load: 8 float4 per lane row
        const float4* g = reinterpret_cast<const float4*>(src)
                        + (size_t)base * (H / 4) + coff4;
        for (int idx = tid; idx < nl * 8; idx += LPB) {
            int l = idx >> 3, j = idx & 7;
            float4 v = g[(size_t)l * (H / 4) + j];
            float* d = &xs[l * XROW + j * 4];
            d[0] = v.x; d[1] = v.y; d[2] = v.z; d[3] = v.w;
        }
        __syncthreads();

        if (tid < nl) {
            const float* xr = &xs[tid * XROW];
#pragma unroll
            for (int c = 0; c < 32; c++) {
                float x = xr[c];
                unsigned long long xx;
                asm("mov.b64 %0, {%1, %1};" : "=l"(xx) : "f"(x));
                const unsigned long long* wr =
                    reinterpret_cast<const unsigned long long*>(&w1s[(kbase + c) * 16]);
#pragma unroll
                for (int q = 0; q < 8; q++)
                    asm("fma.rn.f32x2 %0, %1, %2, %0;"
                        : "+l"(hp[q]) : "l"(xx), "l"(wr[q]));
            }
        }
    }

    float ex = 0.0f;
    int   s  = NSEG;                 // dump slot for OOB lanes
    if (tid < nl) {
        float sc = b2s;
#pragma unroll
        for (int q = 0; q < 8; q++) {
            float lo, hi;
            asm("mov.b64 {%0, %1}, %2;" : "=f"(lo), "=f"(hi) : "l"(hp[q]));
            sc = fmaf(fmaxf(lo, 0.0f), w2s[2 * q + 0], sc);
            sc = fmaf(fmaxf(hi, 0.0f), w2s[2 * q + 1], sc);
        }
        s  = seg[base + tid];
        ex = __expf(sc);             // scores ~|2|: no max-shift needed
        seg_s[tid] = s;
    }
    ex_s[tid] = ex;

    // ---- per-segment sum of ex (sorted ids -> warp-segmented reduce) ----
    {
        const int li = tid & 31;
        float v = ex;
#pragma unroll
        for (int o = 1; o < 32; o <<= 1) {
            float u  = __shfl_down_sync(0xffffffffu, v, o);
            int   s2 = __shfl_down_sync(0xffffffffu, s, o);
            if (li + o < 32 && s2 == s) v += u;
        }
        int sp = __shfl_up_sync(0xffffffffu, s, 1);
        if ((li == 0 || sp != s) && v != 0.0f)
            atomicAdd(&g_seg_sum[s], v);
    }
    __syncthreads();

    // ---- build ordered run boundaries over [0, nl) ----
    int flag = 0;
    if (tid < nl) flag = (tid == 0) || (seg_s[tid] != seg_s[tid - 1]);
    unsigned m = __ballot_sync(0xffffffffu, flag);
    const int wid = tid >> 5, li = tid & 31;
    if (li == 0) warp_cnt[wid] = __popc(m);
    __syncthreads();
    if (tid == 0) {
        int tot = 0;
#pragma unroll
        for (int w = 0; w < NWARP; w++) { int c = warp_cnt[w]; warp_cnt[w] = tot; tot += c; }
        nruns_s = tot;
        run_start[tot] = nl;
    }
    __syncthreads();
    if (flag)
        run_start[warp_cnt[wid] + __popc(m & ((1u << li) - 1u))] = tid;
    __syncthreads();

    // ---- phase 2: unnormalized pooling, one feature column per thread ----
    const float* src2;
    if (tid < 64)       src2 = ht   + tid;
    else if (tid < 128) src2 = info + (tid - 64);
    else                src2 = fut  + (tid - 128);
    src2 += (size_t)base * H;

    const int nruns = nruns_s;
    for (int r = 0; r < nruns; r++) {
        const int st = run_start[r];
        const int en = run_start[r + 1];
        const int sr = seg_s[st];
        float a0 = 0.f, a1 = 0.f, a2 = 0.f, a3 = 0.f;
        int i = st;
        for (; i + 4 <= en; i += 4) {
            a0 = fmaf(ex_s[i    ], src2[(size_t)(i    ) * H], a0);
            a1 = fmaf(ex_s[i + 1], src2[(size_t)(i + 1) * H], a1);
            a2 = fmaf(ex_s[i + 2], src2[(size_t)(i + 2) * H], a2);
            a3 = fmaf(ex_s[i + 3], src2[(size_t)(i + 3) * H], a3);
        }
        for (; i < en; i++)
            a0 = fmaf(ex_s[i], src2[(size_t)i * H], a0);
        float acc = (a0 + a1) + (a2 + a3);
        atomicAdd(&out[sr * 192 + tid], acc);
    }
}

// ---------------- kernel 2: normalize out by seg_sum ----------------
__global__ void normalize_kernel(float* __restrict__ out) {
    int i = blockIdx.x * blockDim.x + threadIdx.x;   // i < NSEG*192
    if (i < NSEG * 192)
        out[i] /= g_seg_sum[i / 192];
}

// ---------------- launch ----------------
extern "C" void kernel_launch(void* const* d_in, const int* in_sizes, int n_in,
                              void* d_out, int out_size)
{
    const float* ht   = (const float*)d_in[0];
    const float* info = (const float*)d_in[1];
    const float* fut  = (const float*)d_in[2];
    const int*   seg  = (const int*)  d_in[3];
    const float* w1   = (const float*)d_in[4];
    const float* b1   = (const float*)d_in[5];
    const float* w2   = (const float*)d_in[6];
    const float* b2   = (const float*)d_in[7];
    float* out = (float*)d_out;

    int M = in_sizes[0] / H;

    int init_n = out_size > (NSEG + 1) ? out_size : (NSEG + 1);
    init_kernel<<<(init_n + 255) / 256, 256>>>(out, out_size);

    fused_kernel<<<(M + LPB - 1) / LPB, LPB>>>(ht, info, fut, seg,
                                               w1, b1, w2, b2, out, M);

    normalize_kernel<<<(NSEG * 192 + 255) / 256, 256>>>(out);
}